// round 15
// baseline (speedup 1.0000x reference)
#include <cuda_runtime.h>
#include <math.h>
#include <float.h>

#define BN_TOTAL 2048
#define NB 256
#define FULLM 0xffffffffu

// ---------------- device scratch ----------------
__device__ float2 g_p2[BN_TOTAL];
__device__ float4 g_L[BN_TOTAL];
__device__ float  g_sub[8][NB][NB];   // contiguous per-batch diagonal blocks

// ---------------- serial Jacobi (3x3) ---------------
__device__ void jacobi_sym(double* A, double* V, int n) {
    for (int i = 0; i < n; i++)
        for (int j = 0; j < n; j++)
            V[i * n + j] = (i == j) ? 1.0 : 0.0;
    double fro2 = 0.0;
    for (int i = 0; i < n * n; i++) fro2 += A[i] * A[i];
    double thresh = 1e-28 * fro2 + 1e-300;
    for (int sweep = 0; sweep < 10; sweep++) {
        double off = 0.0;
        for (int p = 0; p < n - 1; p++)
            for (int q = p + 1; q < n; q++)
                off += A[p * n + q] * A[p * n + q];
        if (off < thresh) break;
        for (int p = 0; p < n - 1; p++) {
            for (int q = p + 1; q < n; q++) {
                double apq = A[p * n + q];
                if (fabs(apq) < 1e-300) continue;
                double app = A[p * n + p], aqq = A[q * n + q];
                double theta = (aqq - app) / (2.0 * apq);
                double t = ((theta >= 0.0) ? 1.0 : -1.0) /
                           (fabs(theta) + sqrt(theta * theta + 1.0));
                double c = 1.0 / sqrt(t * t + 1.0);
                double s = t * c;
                for (int k = 0; k < n; k++) {
                    double akp = A[k * n + p], akq = A[k * n + q];
                    A[k * n + p] = c * akp - s * akq;
                    A[k * n + q] = s * akp + c * akq;
                }
                for (int k = 0; k < n; k++) {
                    double apk = A[p * n + k], aqk = A[q * n + k];
                    A[p * n + k] = c * apk - s * aqk;
                    A[q * n + k] = s * apk + c * aqk;
                }
                for (int k = 0; k < n; k++) {
                    double vkp = V[k * n + p], vkq = V[k * n + q];
                    V[k * n + p] = c * vkp - s * vkq;
                    V[k * n + q] = s * vkp + c * vkq;
                }
            }
        }
    }
}

__device__ double block_reduce_sum(double v, double* sred) {
    int t = threadIdx.x;
    sred[t] = v;
    __syncthreads();
    for (int o = 128; o > 0; o >>= 1) {
        if (t < o) sred[t] += sred[t + o];
        __syncthreads();
    }
    double r = sred[0];
    __syncthreads();
    return r;
}

// ---------------- K1: model fit ----------------
__global__ void __launch_bounds__(256) k1_model(const float* __restrict__ theta,
                                                const float* __restrict__ feat1,
                                                const float* __restrict__ feat2) {
    __shared__ double sred[256];
    __shared__ double sh_AtA[45];
    __shared__ double sh_F[9];
    int t = threadIdx.x;

    double th = (double)theta[0];
    double c = cos(th), s = sin(th);

    float2 p1l[8], p2l[8];
    double s1x = 0, s1y = 0, s2x = 0, s2y = 0;
#pragma unroll
    for (int k = 0; k < 8; k++) {
        int idx = t + (k << 8);
        const float* f1p = feat1 + (size_t)idx * 130;
        const float* f2p = feat2 + (size_t)idx * 130;
        float p1x = truncf(f2p[0]);
        float p1y = truncf(f2p[1]);
        double ax = (double)f1p[0] - 320.0;
        double ay = 240.0 - (double)f1p[1];
        double calx = rint(c * ax - s * ay);
        double caly = rint(s * ax + c * ay);
        float p2x = (float)trunc(calx + 320.0);
        float p2y = (float)trunc(240.0 - caly);
        p1l[k] = make_float2(p1x, p1y);
        p2l[k] = make_float2(p2x, p2y);
        g_p2[idx] = p2l[k];
        s1x += p1x; s1y += p1y; s2x += p2x; s2y += p2y;
    }
    double m1x = block_reduce_sum(s1x, sred) * (1.0 / 2048.0);
    double m1y = block_reduce_sum(s1y, sred) * (1.0 / 2048.0);
    double m2x = block_reduce_sum(s2x, sred) * (1.0 / 2048.0);
    double m2y = block_reduce_sum(s2y, sred) * (1.0 / 2048.0);

    double a1 = 0, a2 = 0;
#pragma unroll
    for (int k = 0; k < 8; k++) {
        double dx = (double)p1l[k].x - m1x, dy = (double)p1l[k].y - m1y;
        a1 += sqrt(dx * dx + dy * dy);
        double ex = (double)p2l[k].x - m2x, ey = (double)p2l[k].y - m2y;
        a2 += sqrt(ex * ex + ey * ey);
    }
    double d1 = block_reduce_sum(a1, sred) * (1.0 / 2048.0);
    double d2 = block_reduce_sum(a2, sred) * (1.0 / 2048.0);
    double sc1 = sqrt(2.0) / d1;
    double sc2 = sqrt(2.0) / d2;

    double m[45];
#pragma unroll
    for (int e = 0; e < 45; e++) m[e] = 0.0;
#pragma unroll
    for (int k = 0; k < 8; k++) {
        double u1 = ((double)p1l[k].x - m1x) * sc1;
        double v1 = ((double)p1l[k].y - m1y) * sc1;
        double u2 = ((double)p2l[k].x - m2x) * sc2;
        double v2 = ((double)p2l[k].y - m2y) * sc2;
        double a[9] = {u2 * u1, u2 * v1, u2, v2 * u1, v2 * v1, v2, u1, v1, 1.0};
        int e = 0;
#pragma unroll
        for (int p = 0; p < 9; p++)
#pragma unroll
            for (int q = p; q < 9; q++)
                m[e++] += a[p] * a[q];
    }
    if (t < 45) sh_AtA[t] = 0.0;
    __syncthreads();
    int lane = t & 31;
#pragma unroll
    for (int e = 0; e < 45; e++) {
        double v = m[e];
        for (int o = 16; o; o >>= 1) v += __shfl_down_sync(FULLM, v, o);
        if (lane == 0) atomicAdd(&sh_AtA[e], v);
    }
    __syncthreads();

    if (t == 0) {
        double A[81];
        {
            int e = 0;
            for (int p = 0; p < 9; p++)
                for (int q = p; q < 9; q++) {
                    A[p * 9 + q] = sh_AtA[e];
                    A[q * 9 + p] = sh_AtA[e];
                    e++;
                }
        }
        double L[81], dinv[9];
        for (int cc = 0; cc < 9; cc++) {
            double d = A[cc * 9 + cc];
            for (int k = 0; k < cc; k++) d -= L[cc * 9 + k] * L[cc * 9 + k];
            double lc = sqrt(d);
            L[cc * 9 + cc] = lc;
            double invl = 1.0 / lc;
            dinv[cc] = invl;
            for (int r = cc + 1; r < 9; r++) {
                double s2 = A[r * 9 + cc];
                for (int k = 0; k < cc; k++) s2 -= L[r * 9 + k] * L[cc * 9 + k];
                L[r * 9 + cc] = s2 * invl;
            }
        }
        double x[9];
        for (int i = 0; i < 9; i++) x[i] = 1.0 / (double)(i + 1);
        for (int it = 0; it < 25; it++) {
            double z[9], y[9];
            for (int r = 0; r < 9; r++) {
                double acc = x[r];
                for (int k = 0; k < r; k++) acc -= L[r * 9 + k] * z[k];
                z[r] = acc * dinv[r];
            }
            for (int r = 8; r >= 0; r--) {
                double acc = z[r];
                for (int k = r + 1; k < 9; k++) acc -= L[k * 9 + r] * y[k];
                y[r] = acc * dinv[r];
            }
            double nrm = 0.0;
            for (int i = 0; i < 9; i++) nrm += y[i] * y[i];
            double inv = 1.0 / sqrt(nrm);
            for (int i = 0; i < 9; i++) x[i] = y[i] * inv;
        }
        double F[9];
        for (int i = 0; i < 9; i++) F[i] = x[i];

        double G[9], V3[9];
        for (int r = 0; r < 3; r++)
            for (int cc = 0; cc < 3; cc++) {
                double acc = 0;
                for (int kk = 0; kk < 3; kk++) acc += F[kk * 3 + r] * F[kk * 3 + cc];
                G[r * 3 + cc] = acc;
            }
        jacobi_sym(G, V3, 3);
        int mi3 = 0;
        for (int i = 1; i < 3; i++)
            if (G[i * 3 + i] < G[mi3 * 3 + mi3]) mi3 = i;
        double v3[3] = {V3[0 * 3 + mi3], V3[1 * 3 + mi3], V3[2 * 3 + mi3]};
        double Fv[3];
        for (int r = 0; r < 3; r++)
            Fv[r] = F[r * 3 + 0] * v3[0] + F[r * 3 + 1] * v3[1] + F[r * 3 + 2] * v3[2];
        double F2[9];
        for (int r = 0; r < 3; r++)
            for (int cc = 0; cc < 3; cc++)
                F2[r * 3 + cc] = F[r * 3 + cc] - Fv[r] * v3[cc];

        double M1[9];
        for (int cc = 0; cc < 3; cc++) {
            M1[0 * 3 + cc] = sc2 * F2[0 * 3 + cc];
            M1[1 * 3 + cc] = sc2 * F2[1 * 3 + cc];
            M1[2 * 3 + cc] = (-sc2 * m2x) * F2[0 * 3 + cc] +
                             (-sc2 * m2y) * F2[1 * 3 + cc] + F2[2 * 3 + cc];
        }
        double M[9];
        for (int r = 0; r < 3; r++) {
            M[r * 3 + 0] = M1[r * 3 + 0] * sc1;
            M[r * 3 + 1] = M1[r * 3 + 1] * sc1;
            M[r * 3 + 2] = M1[r * 3 + 0] * (-sc1 * m1x) +
                           M1[r * 3 + 1] * (-sc1 * m1y) + M1[r * 3 + 2];
        }
        double inv = 1.0 / M[8];
        for (int i = 0; i < 9; i++) sh_F[i] = M[i] * inv;
    }
    __syncthreads();

#pragma unroll
    for (int k = 0; k < 8; k++) {
        int idx = t + (k << 8);
        double px = (double)p1l[k].x, py = (double)p1l[k].y;
        double L0 = px * sh_F[0] + py * sh_F[3] + sh_F[6];
        double L1 = px * sh_F[1] + py * sh_F[4] + sh_F[7];
        double L2 = px * sh_F[2] + py * sh_F[5] + sh_F[8];
        g_L[idx] = make_float4((float)L0, (float)L1, (float)L2, 0.0f);
    }
}

// ---------------- K2 body: one 128x128 cost tile ----------------
__device__ __forceinline__ void k2_tile_body(const float* __restrict__ feat1,
                                             const float* __restrict__ feat2,
                                             float* __restrict__ C,
                                             int bi, int bj, bool diag,
                                             float (*As)[128], float (*Bs)[128]) {
    int t = threadIdx.x;
    int tx = t & 15, ty = t >> 4;
    int lr = t & 127, lh = (t >> 7) << 2;

    float acc[8][8];
#pragma unroll
    for (int mm = 0; mm < 8; mm++)
#pragma unroll
        for (int nn = 0; nn < 8; nn++) acc[mm][nn] = 0.0f;

    const float* A0 = feat1 + (size_t)(bi + lr) * 130 + 2;
    const float* B0 = feat2 + (size_t)(bj + lr) * 130 + 2;

    for (int k0 = 0; k0 < 128; k0 += 8) {
        float2 a0 = *(const float2*)(A0 + k0 + lh);
        float2 a1 = *(const float2*)(A0 + k0 + lh + 2);
        float2 b0 = *(const float2*)(B0 + k0 + lh);
        float2 b1 = *(const float2*)(B0 + k0 + lh + 2);
        As[lh + 0][lr] = a0.x; As[lh + 1][lr] = a0.y;
        As[lh + 2][lr] = a1.x; As[lh + 3][lr] = a1.y;
        Bs[lh + 0][lr] = b0.x; Bs[lh + 1][lr] = b0.y;
        Bs[lh + 2][lr] = b1.x; Bs[lh + 3][lr] = b1.y;
        __syncthreads();
#pragma unroll
        for (int kk = 0; kk < 8; kk++) {
            float a[8], b[8];
            *(float4*)&a[0] = *(const float4*)&As[kk][ty << 3];
            *(float4*)&a[4] = *(const float4*)&As[kk][(ty << 3) + 4];
            *(float4*)&b[0] = *(const float4*)&Bs[kk][tx << 3];
            *(float4*)&b[4] = *(const float4*)&Bs[kk][(tx << 3) + 4];
#pragma unroll
            for (int mm = 0; mm < 8; mm++)
#pragma unroll
                for (int nn = 0; nn < 8; nn++)
                    acc[mm][nn] += fabsf(a[mm] - b[nn]);
        }
        __syncthreads();
    }

    float4 Lm[8];
    float2 Pn[8];
#pragma unroll
    for (int mm = 0; mm < 8; mm++) Lm[mm] = g_L[bi + (ty << 3) + mm];
#pragma unroll
    for (int nn = 0; nn < 8; nn++) Pn[nn] = g_p2[bj + (tx << 3) + nn];
#pragma unroll
    for (int mm = 0; mm < 8; mm++)
#pragma unroll
        for (int nn = 0; nn < 8; nn++)
            acc[mm][nn] += fabsf(Lm[mm].x * Pn[nn].x + Lm[mm].y * Pn[nn].y + Lm[mm].z);

    int bb = bi >> 8;
    int ri0 = bi & 255, rj0 = bj & 255;
#pragma unroll
    for (int mm = 0; mm < 8; mm++) {
        float4 v0 = make_float4(acc[mm][0], acc[mm][1], acc[mm][2], acc[mm][3]);
        float4 v1 = make_float4(acc[mm][4], acc[mm][5], acc[mm][6], acc[mm][7]);
        float* dst = C + (size_t)(bi + (ty << 3) + mm) * 2048 + bj + (tx << 3);
        ((float4*)dst)[0] = v0;
        ((float4*)dst)[1] = v1;
        if (diag) {
            float* sd = &g_sub[bb][ri0 + (ty << 3) + mm][rj0 + (tx << 3)];
            ((float4*)sd)[0] = v0;
            ((float4*)sd)[1] = v1;
        }
    }
}

// diagonal tiles only: grid (2, 16)
__global__ void __launch_bounds__(256) k2_diag(const float* __restrict__ feat1,
                                               const float* __restrict__ feat2,
                                               float* __restrict__ C) {
    __shared__ float As[8][128];
    __shared__ float Bs[8][128];
    int bb = blockIdx.y >> 1;
    int ri = blockIdx.y & 1;
    int rj = blockIdx.x;
    int bi = (bb << 8) + (ri << 7);
    int bj = (bb << 8) + (rj << 7);
    k2_tile_body(feat1, feat2, C, bi, bj, true, As, Bs);
}

// ---------------- fused: blocks 0-7 LAP, blocks 8-231 off-diag tiles -------
__device__ __forceinline__ unsigned long long packkey(double v, int j) {
    unsigned long long b = (unsigned long long)__double_as_longlong(v);
    b = (b & 0x8000000000000000ull) ? ~b : (b | 0x8000000000000000ull);
    return (b & ~0xFFull) | (unsigned)j;
}
__device__ __forceinline__ double unpackval(unsigned long long k) {
    k &= ~0xFFull;
    if (k & 0x8000000000000000ull) k ^= 0x8000000000000000ull;
    else k = ~k;
    return __longlong_as_double((long long)k);
}

__global__ void __launch_bounds__(256) k3_fused(const float* __restrict__ feat1,
                                                const float* __restrict__ feat2,
                                                float* __restrict__ C,
                                                float* __restrict__ out_matches) {
    __shared__ float As[8][128];
    __shared__ float Bs[8][128];
    __shared__ double s_v[NB], s_u[NB], s_srec[NB];
    __shared__ int s_x[NB], s_y[NB], s_path[NB], s_free[NB];
    __shared__ int s_rowwin[NB], s_req[NB];
    __shared__ unsigned long long s_wm[3][8];   // 3-buffer rotation
    __shared__ int s_nfree;

    if (blockIdx.x >= 8) {
        // ---- off-diagonal cost tile ----
        int idx = blockIdx.x - 8;           // 0..223
        int rrow = idx / 14;                // bi tile row 0..15
        int c14 = idx % 14;
        int bb = rrow >> 1;
        int cc = (c14 >= (bb << 1)) ? c14 + 2 : c14;   // skip 2 diagonal cols
        int bi = rrow << 7;
        int bj = cc << 7;
        k2_tile_body(feat1, feat2, C, bi, bj, false, As, Bs);
        return;
    }

    // ---- LAP on diagonal block ----
    int j = threadIdx.x;
    int b = blockIdx.x;
    const float* Cb = &g_sub[b][0][0];

    // Phase A: v[j] = colmin + argmin row; greedy round 1
    float cm = FLT_MAX;
    int am = 0;
#pragma unroll 8
    for (int i = 0; i < NB; i++) {
        float cv = Cb[(size_t)i * NB + j];
        if (cv < cm) { cm = cv; am = i; }
    }
    s_v[j] = (double)cm;
    s_x[j] = -1;
    s_y[j] = -1;
    s_rowwin[j] = 0x7fffffff;
    s_req[j] = 0x7fffffff;
    __syncthreads();
    atomicMin(&s_rowwin[am], j);
    __syncthreads();
    if (s_rowwin[am] == j) { s_x[am] = j; s_y[j] = am; }
    __syncthreads();

    // Phase B: u[r] = rowmin + argmin; greedy round 2
    int r = j;
    double um = DBL_MAX;
    int jm = 0;
    {
        const float* rp = Cb + (size_t)r * NB;
        for (int q = 0; q < NB; q++) {
            double rc = (double)rp[q] - s_v[q];
            if (rc < um) { um = rc; jm = q; }
        }
    }
    s_u[r] = um;
    if (s_x[r] < 0 && s_y[jm] < 0) atomicMin(&s_req[jm], r);
    __syncthreads();
    if (s_x[r] < 0 && s_req[jm] == r && s_y[jm] < 0) {
        s_x[r] = jm;
        s_y[jm] = r;
    }
    __syncthreads();

    if (j == 0) {
        int n = 0;
        for (int rr = 0; rr < NB; rr++)
            if (s_x[rr] < 0) s_free[n++] = rr;
        s_nfree = n;
    }
    __syncthreads();

    // exact shortest augmenting path per free row
    double vj = s_v[j];
    int nfree = s_nfree;
    int lane = j & 31, warp = j >> 5;

    for (int f = 0; f < nfree; f++) {
        int cur = s_free[f];
        double shortest = DBL_MAX;
        int pathreg = cur;
        bool rem = true;
        bool inSR = (j == cur);
        int i = cur;
        double bvj = -s_u[cur] - vj;
        double minv = 0.0;
        int sink = -1;
        int buf = 0;

        // reset all 3 reduction buffers for this augment
        if (j < 24) s_wm[j >> 3][j & 7] = ~0ull;
        __syncthreads();

        while (true) {
            float cf = Cb[(size_t)i * NB + j];
            unsigned long long fullkey = ~0ull;
            unsigned kq = 0xFFFFFFFFu;
            if (rem) {
                double rd = (double)cf + bvj;
                if (rd < shortest) { shortest = rd; pathreg = i; }
                fullkey = packkey(shortest, j);
                kq = (unsigned)(fullkey >> 32);
            }
            // warp-level coarse min (REDUX), exact resolve via u64 atomicMin
            unsigned wmin = __reduce_min_sync(FULLM, kq);
            if (rem && kq == wmin)
                atomicMin(&s_wm[buf][warp], fullkey);
            // reset next buffer (used in next iteration, after this barrier)
            int nbuf = (buf + 1) % 3;
            if (lane == 0) s_wm[nbuf][warp] = ~0ull;
            __syncthreads();
            unsigned long long mn = s_wm[buf][0];
#pragma unroll
            for (int w = 1; w < 8; w++) {
                unsigned long long t2 = s_wm[buf][w];
                if (t2 < mn) mn = t2;
            }
            buf = nbuf;
            int jpos = (int)(mn & 0xFF);
            minv = unpackval(mn);
            if (j == jpos) {
                rem = false;
                s_srec[j] = minv;
                s_path[j] = pathreg;
            }
            int r4c = s_y[jpos];
            if (r4c < 0) { sink = jpos; break; }
            i = r4c;
            if (j == i) inSR = true;
            bvj = minv - s_u[i] - vj;
        }
        __syncthreads();

        if (!rem) vj -= minv - s_srec[j];
        if (inSR) {
            if (j == cur) s_u[j] += minv;
            else s_u[j] += minv - s_srec[s_x[j]];
        }
        __syncthreads();

        if (j == 0) {
            int jj = sink;
            while (true) {
                int i2 = s_path[jj];
                s_y[jj] = i2;
                int t2 = s_x[i2];
                s_x[i2] = jj;
                jj = t2;
                if (i2 == cur) break;
            }
        }
        __syncthreads();
    }

    out_matches[b * 512 + j]       = (float)j;
    out_matches[b * 512 + 256 + j] = (float)s_x[j];
}

// ---------------- launch ----------------
extern "C" void kernel_launch(void* const* d_in, const int* in_sizes, int n_in,
                              void* d_out, int out_size) {
    const float* theta = (const float*)d_in[0];
    const float* feat1 = (const float*)d_in[1];
    const float* feat2 = (const float*)d_in[2];
    float* C = (float*)d_out;
    float* matches = C + (size_t)2048 * 2048;

    k1_model<<<1, 256>>>(theta, feat1, feat2);
    k2_diag<<<dim3(2, 16), 256>>>(feat1, feat2, C);
    k3_fused<<<232, 256>>>(feat1, feat2, C, matches);
}

// round 16
// speedup vs baseline: 1.0264x; 1.0264x over previous
#include <cuda_runtime.h>
#include <math.h>
#include <float.h>

#define BN_TOTAL 2048
#define NB 256
#define FULLM 0xffffffffu

// ---------------- device scratch ----------------
__device__ float2 g_p2[BN_TOTAL];
__device__ float4 g_L[BN_TOTAL];
__device__ float  g_sub[8][NB][NB];   // diag blocks: desc-only after kA, final after kB phase A

// ---------------- serial Jacobi (3x3) ---------------
__device__ void jacobi_sym(double* A, double* V, int n) {
    for (int i = 0; i < n; i++)
        for (int j = 0; j < n; j++)
            V[i * n + j] = (i == j) ? 1.0 : 0.0;
    double fro2 = 0.0;
    for (int i = 0; i < n * n; i++) fro2 += A[i] * A[i];
    double thresh = 1e-28 * fro2 + 1e-300;
    for (int sweep = 0; sweep < 10; sweep++) {
        double off = 0.0;
        for (int p = 0; p < n - 1; p++)
            for (int q = p + 1; q < n; q++)
                off += A[p * n + q] * A[p * n + q];
        if (off < thresh) break;
        for (int p = 0; p < n - 1; p++) {
            for (int q = p + 1; q < n; q++) {
                double apq = A[p * n + q];
                if (fabs(apq) < 1e-300) continue;
                double app = A[p * n + p], aqq = A[q * n + q];
                double theta = (aqq - app) / (2.0 * apq);
                double t = ((theta >= 0.0) ? 1.0 : -1.0) /
                           (fabs(theta) + sqrt(theta * theta + 1.0));
                double c = 1.0 / sqrt(t * t + 1.0);
                double s = t * c;
                for (int k = 0; k < n; k++) {
                    double akp = A[k * n + p], akq = A[k * n + q];
                    A[k * n + p] = c * akp - s * akq;
                    A[k * n + q] = s * akp + c * akq;
                }
                for (int k = 0; k < n; k++) {
                    double apk = A[p * n + k], aqk = A[q * n + k];
                    A[p * n + k] = c * apk - s * aqk;
                    A[q * n + k] = s * apk + c * aqk;
                }
                for (int k = 0; k < n; k++) {
                    double vkp = V[k * n + p], vkq = V[k * n + q];
                    V[k * n + p] = c * vkp - s * vkq;
                    V[k * n + q] = s * vkp + c * vkq;
                }
            }
        }
    }
}

__device__ double block_reduce_sum(double v, double* sred) {
    int t = threadIdx.x;
    sred[t] = v;
    __syncthreads();
    for (int o = 128; o > 0; o >>= 1) {
        if (t < o) sred[t] += sred[t + o];
        __syncthreads();
    }
    double r = sred[0];
    __syncthreads();
    return r;
}

// ---------------- model fit body (runs in kA block 32) ----------------
__device__ void model_fit_body(const float* __restrict__ theta,
                               const float* __restrict__ feat1,
                               const float* __restrict__ feat2,
                               double* sred, double* sh_AtA, double* sh_F) {
    int t = threadIdx.x;

    double th = (double)theta[0];
    double c = cos(th), s = sin(th);

    float2 p1l[8], p2l[8];
    double s1x = 0, s1y = 0, s2x = 0, s2y = 0;
#pragma unroll
    for (int k = 0; k < 8; k++) {
        int idx = t + (k << 8);
        const float* f1p = feat1 + (size_t)idx * 130;
        const float* f2p = feat2 + (size_t)idx * 130;
        float p1x = truncf(f2p[0]);
        float p1y = truncf(f2p[1]);
        double ax = (double)f1p[0] - 320.0;
        double ay = 240.0 - (double)f1p[1];
        double calx = rint(c * ax - s * ay);
        double caly = rint(s * ax + c * ay);
        float p2x = (float)trunc(calx + 320.0);
        float p2y = (float)trunc(240.0 - caly);
        p1l[k] = make_float2(p1x, p1y);
        p2l[k] = make_float2(p2x, p2y);
        g_p2[idx] = p2l[k];
        s1x += p1x; s1y += p1y; s2x += p2x; s2y += p2y;
    }
    double m1x = block_reduce_sum(s1x, sred) * (1.0 / 2048.0);
    double m1y = block_reduce_sum(s1y, sred) * (1.0 / 2048.0);
    double m2x = block_reduce_sum(s2x, sred) * (1.0 / 2048.0);
    double m2y = block_reduce_sum(s2y, sred) * (1.0 / 2048.0);

    double a1 = 0, a2 = 0;
#pragma unroll
    for (int k = 0; k < 8; k++) {
        double dx = (double)p1l[k].x - m1x, dy = (double)p1l[k].y - m1y;
        a1 += sqrt(dx * dx + dy * dy);
        double ex = (double)p2l[k].x - m2x, ey = (double)p2l[k].y - m2y;
        a2 += sqrt(ex * ex + ey * ey);
    }
    double d1 = block_reduce_sum(a1, sred) * (1.0 / 2048.0);
    double d2 = block_reduce_sum(a2, sred) * (1.0 / 2048.0);
    double sc1 = sqrt(2.0) / d1;
    double sc2 = sqrt(2.0) / d2;

    double m[45];
#pragma unroll
    for (int e = 0; e < 45; e++) m[e] = 0.0;
#pragma unroll
    for (int k = 0; k < 8; k++) {
        double u1 = ((double)p1l[k].x - m1x) * sc1;
        double v1 = ((double)p1l[k].y - m1y) * sc1;
        double u2 = ((double)p2l[k].x - m2x) * sc2;
        double v2 = ((double)p2l[k].y - m2y) * sc2;
        double a[9] = {u2 * u1, u2 * v1, u2, v2 * u1, v2 * v1, v2, u1, v1, 1.0};
        int e = 0;
#pragma unroll
        for (int p = 0; p < 9; p++)
#pragma unroll
            for (int q = p; q < 9; q++)
                m[e++] += a[p] * a[q];
    }
    if (t < 45) sh_AtA[t] = 0.0;
    __syncthreads();
    int lane = t & 31;
#pragma unroll
    for (int e = 0; e < 45; e++) {
        double v = m[e];
        for (int o = 16; o; o >>= 1) v += __shfl_down_sync(FULLM, v, o);
        if (lane == 0) atomicAdd(&sh_AtA[e], v);
    }
    __syncthreads();

    if (t == 0) {
        double A[81];
        {
            int e = 0;
            for (int p = 0; p < 9; p++)
                for (int q = p; q < 9; q++) {
                    A[p * 9 + q] = sh_AtA[e];
                    A[q * 9 + p] = sh_AtA[e];
                    e++;
                }
        }
        double L[81], dinv[9];
        for (int cc = 0; cc < 9; cc++) {
            double d = A[cc * 9 + cc];
            for (int k = 0; k < cc; k++) d -= L[cc * 9 + k] * L[cc * 9 + k];
            double lc = sqrt(d);
            L[cc * 9 + cc] = lc;
            double invl = 1.0 / lc;
            dinv[cc] = invl;
            for (int r = cc + 1; r < 9; r++) {
                double s2 = A[r * 9 + cc];
                for (int k = 0; k < cc; k++) s2 -= L[r * 9 + k] * L[cc * 9 + k];
                L[r * 9 + cc] = s2 * invl;
            }
        }
        double x[9];
        for (int i = 0; i < 9; i++) x[i] = 1.0 / (double)(i + 1);
        for (int it = 0; it < 25; it++) {
            double z[9], y[9];
            for (int r = 0; r < 9; r++) {
                double acc = x[r];
                for (int k = 0; k < r; k++) acc -= L[r * 9 + k] * z[k];
                z[r] = acc * dinv[r];
            }
            for (int r = 8; r >= 0; r--) {
                double acc = z[r];
                for (int k = r + 1; k < 9; k++) acc -= L[k * 9 + r] * y[k];
                y[r] = acc * dinv[r];
            }
            double nrm = 0.0;
            for (int i = 0; i < 9; i++) nrm += y[i] * y[i];
            double inv = 1.0 / sqrt(nrm);
            for (int i = 0; i < 9; i++) x[i] = y[i] * inv;
        }
        double F[9];
        for (int i = 0; i < 9; i++) F[i] = x[i];

        double G[9], V3[9];
        for (int r = 0; r < 3; r++)
            for (int cc = 0; cc < 3; cc++) {
                double acc = 0;
                for (int kk = 0; kk < 3; kk++) acc += F[kk * 3 + r] * F[kk * 3 + cc];
                G[r * 3 + cc] = acc;
            }
        jacobi_sym(G, V3, 3);
        int mi3 = 0;
        for (int i = 1; i < 3; i++)
            if (G[i * 3 + i] < G[mi3 * 3 + mi3]) mi3 = i;
        double v3[3] = {V3[0 * 3 + mi3], V3[1 * 3 + mi3], V3[2 * 3 + mi3]};
        double Fv[3];
        for (int r = 0; r < 3; r++)
            Fv[r] = F[r * 3 + 0] * v3[0] + F[r * 3 + 1] * v3[1] + F[r * 3 + 2] * v3[2];
        double F2[9];
        for (int r = 0; r < 3; r++)
            for (int cc = 0; cc < 3; cc++)
                F2[r * 3 + cc] = F[r * 3 + cc] - Fv[r] * v3[cc];

        double M1[9];
        for (int cc = 0; cc < 3; cc++) {
            M1[0 * 3 + cc] = sc2 * F2[0 * 3 + cc];
            M1[1 * 3 + cc] = sc2 * F2[1 * 3 + cc];
            M1[2 * 3 + cc] = (-sc2 * m2x) * F2[0 * 3 + cc] +
                             (-sc2 * m2y) * F2[1 * 3 + cc] + F2[2 * 3 + cc];
        }
        double M[9];
        for (int r = 0; r < 3; r++) {
            M[r * 3 + 0] = M1[r * 3 + 0] * sc1;
            M[r * 3 + 1] = M1[r * 3 + 1] * sc1;
            M[r * 3 + 2] = M1[r * 3 + 0] * (-sc1 * m1x) +
                           M1[r * 3 + 1] * (-sc1 * m1y) + M1[r * 3 + 2];
        }
        double inv = 1.0 / M[8];
        for (int i = 0; i < 9; i++) sh_F[i] = M[i] * inv;
    }
    __syncthreads();

#pragma unroll
    for (int k = 0; k < 8; k++) {
        int idx = t + (k << 8);
        double px = (double)p1l[k].x, py = (double)p1l[k].y;
        double L0 = px * sh_F[0] + py * sh_F[3] + sh_F[6];
        double L1 = px * sh_F[1] + py * sh_F[4] + sh_F[7];
        double L2 = px * sh_F[2] + py * sh_F[5] + sh_F[8];
        g_L[idx] = make_float4((float)L0, (float)L1, (float)L2, 0.0f);
    }
}

// ---------------- cost tile body ----------------
// mode: write_C (with kp epilogue) and/or write_sub (desc-only or full)
__device__ __forceinline__ void k2_tile_body(const float* __restrict__ feat1,
                                             const float* __restrict__ feat2,
                                             float* __restrict__ C,
                                             int bi, int bj,
                                             bool add_kp, bool write_C, bool write_sub,
                                             float (*As)[128], float (*Bs)[128]) {
    int t = threadIdx.x;
    int tx = t & 15, ty = t >> 4;
    int lr = t & 127, lh = (t >> 7) << 2;

    float acc[8][8];
#pragma unroll
    for (int mm = 0; mm < 8; mm++)
#pragma unroll
        for (int nn = 0; nn < 8; nn++) acc[mm][nn] = 0.0f;

    const float* A0 = feat1 + (size_t)(bi + lr) * 130 + 2;
    const float* B0 = feat2 + (size_t)(bj + lr) * 130 + 2;

    for (int k0 = 0; k0 < 128; k0 += 8) {
        float2 a0 = *(const float2*)(A0 + k0 + lh);
        float2 a1 = *(const float2*)(A0 + k0 + lh + 2);
        float2 b0 = *(const float2*)(B0 + k0 + lh);
        float2 b1 = *(const float2*)(B0 + k0 + lh + 2);
        As[lh + 0][lr] = a0.x; As[lh + 1][lr] = a0.y;
        As[lh + 2][lr] = a1.x; As[lh + 3][lr] = a1.y;
        Bs[lh + 0][lr] = b0.x; Bs[lh + 1][lr] = b0.y;
        Bs[lh + 2][lr] = b1.x; Bs[lh + 3][lr] = b1.y;
        __syncthreads();
#pragma unroll
        for (int kk = 0; kk < 8; kk++) {
            float a[8], b[8];
            *(float4*)&a[0] = *(const float4*)&As[kk][ty << 3];
            *(float4*)&a[4] = *(const float4*)&As[kk][(ty << 3) + 4];
            *(float4*)&b[0] = *(const float4*)&Bs[kk][tx << 3];
            *(float4*)&b[4] = *(const float4*)&Bs[kk][(tx << 3) + 4];
#pragma unroll
            for (int mm = 0; mm < 8; mm++)
#pragma unroll
                for (int nn = 0; nn < 8; nn++)
                    acc[mm][nn] += fabsf(a[mm] - b[nn]);
        }
        __syncthreads();
    }

    if (add_kp) {
        float4 Lm[8];
        float2 Pn[8];
#pragma unroll
        for (int mm = 0; mm < 8; mm++) Lm[mm] = g_L[bi + (ty << 3) + mm];
#pragma unroll
        for (int nn = 0; nn < 8; nn++) Pn[nn] = g_p2[bj + (tx << 3) + nn];
#pragma unroll
        for (int mm = 0; mm < 8; mm++)
#pragma unroll
            for (int nn = 0; nn < 8; nn++)
                acc[mm][nn] += fabsf(Lm[mm].x * Pn[nn].x + Lm[mm].y * Pn[nn].y + Lm[mm].z);
    }

    int bb = bi >> 8;
    int ri0 = bi & 255, rj0 = bj & 255;
#pragma unroll
    for (int mm = 0; mm < 8; mm++) {
        float4 v0 = make_float4(acc[mm][0], acc[mm][1], acc[mm][2], acc[mm][3]);
        float4 v1 = make_float4(acc[mm][4], acc[mm][5], acc[mm][6], acc[mm][7]);
        if (write_C) {
            float* dst = C + (size_t)(bi + (ty << 3) + mm) * 2048 + bj + (tx << 3);
            ((float4*)dst)[0] = v0;
            ((float4*)dst)[1] = v1;
        }
        if (write_sub) {
            float* sd = &g_sub[bb][ri0 + (ty << 3) + mm][rj0 + (tx << 3)];
            ((float4*)sd)[0] = v0;
            ((float4*)sd)[1] = v1;
        }
    }
}

// ---------------- kA: 32 desc-only diag tiles || model fit -----------------
__global__ void __launch_bounds__(256) kA(const float* __restrict__ theta,
                                          const float* __restrict__ feat1,
                                          const float* __restrict__ feat2,
                                          float* __restrict__ C) {
    __shared__ float As[8][128];
    __shared__ float Bs[8][128];
    __shared__ double sred[256];
    __shared__ double sh_AtA[45];
    __shared__ double sh_F[9];

    if (blockIdx.x < 32) {
        // diag tiles, desc only -> g_sub (no F dependency)
        int idx = blockIdx.x;
        int bb = idx >> 2;
        int ri = (idx >> 1) & 1;
        int rj = idx & 1;
        int bi = (bb << 8) + (ri << 7);
        int bj = (bb << 8) + (rj << 7);
        k2_tile_body(feat1, feat2, C, bi, bj,
                     /*add_kp=*/false, /*write_C=*/false, /*write_sub=*/true,
                     As, Bs);
        return;
    }
    // block 32: model fit
    model_fit_body(theta, feat1, feat2, sred, sh_AtA, sh_F);
}

// ---------------- kB: blocks 0-7 LAP (kp folded into phase A), 8-231 tiles -
__device__ __forceinline__ unsigned long long packkey(double v, int j) {
    unsigned long long b = (unsigned long long)__double_as_longlong(v);
    b = (b & 0x8000000000000000ull) ? ~b : (b | 0x8000000000000000ull);
    return (b & ~0xFFull) | (unsigned)j;
}
__device__ __forceinline__ double unpackval(unsigned long long k) {
    k &= ~0xFFull;
    if (k & 0x8000000000000000ull) k ^= 0x8000000000000000ull;
    else k = ~k;
    return __longlong_as_double((long long)k);
}

__global__ void __launch_bounds__(256) k3_fused(const float* __restrict__ feat1,
                                                const float* __restrict__ feat2,
                                                float* __restrict__ C,
                                                float* __restrict__ out_matches) {
    __shared__ float As[8][128];
    __shared__ float Bs[8][128];
    __shared__ double s_v[NB], s_u[NB], s_srec[NB];
    __shared__ int s_x[NB], s_y[NB], s_path[NB], s_free[NB];
    __shared__ int s_rowwin[NB], s_req[NB];
    __shared__ unsigned long long s_wm[2][8];
    __shared__ int s_nfree;

    if (blockIdx.x >= 8) {
        // off-diagonal cost tile (desc + kp -> C)
        int idx = blockIdx.x - 8;           // 0..223
        int rrow = idx / 14;
        int c14 = idx % 14;
        int bb = rrow >> 1;
        int cc = (c14 >= (bb << 1)) ? c14 + 2 : c14;
        int bi = rrow << 7;
        int bj = cc << 7;
        k2_tile_body(feat1, feat2, C, bi, bj,
                     /*add_kp=*/true, /*write_C=*/true, /*write_sub=*/false,
                     As, Bs);
        return;
    }

    // ---- LAP on diagonal block (R14 engine; kp epilogue folded into A) ----
    int j = threadIdx.x;
    int b = blockIdx.x;
    float* Cb = &g_sub[b][0][0];
    float* Cdiag = C + (size_t)(b * NB) * 2048 + b * NB;

    // Phase A: finalize cost (desc + kp), colmin + argmin row; greedy round 1
    float p2x, p2y;
    {
        float2 p2 = g_p2[b * NB + j];
        p2x = p2.x; p2y = p2.y;
    }
    float cm = FLT_MAX;
    int am = 0;
#pragma unroll 4
    for (int i = 0; i < NB; i++) {
        float4 Li = g_L[b * NB + i];                 // uniform broadcast
        float desc = Cb[(size_t)i * NB + j];
        float cv = desc + fabsf(Li.x * p2x + Li.y * p2y + Li.z);
        Cb[(size_t)i * NB + j] = cv;
        Cdiag[(size_t)i * 2048 + j] = cv;
        if (cv < cm) { cm = cv; am = i; }            // lowest i on ties
    }
    s_v[j] = (double)cm;
    s_x[j] = -1;
    s_y[j] = -1;
    s_rowwin[j] = 0x7fffffff;
    s_req[j] = 0x7fffffff;
    __syncthreads();      // cost writes visible block-wide; duals init done
    atomicMin(&s_rowwin[am], j);
    __syncthreads();
    if (s_rowwin[am] == j) { s_x[am] = j; s_y[j] = am; }
    __syncthreads();

    // Phase B: u[r] = rowmin + argmin; greedy round 2
    int r = j;
    double um = DBL_MAX;
    int jm = 0;
    {
        const float* rp = Cb + (size_t)r * NB;
        for (int q = 0; q < NB; q++) {
            double rc = (double)rp[q] - s_v[q];
            if (rc < um) { um = rc; jm = q; }
        }
    }
    s_u[r] = um;
    if (s_x[r] < 0 && s_y[jm] < 0) atomicMin(&s_req[jm], r);
    __syncthreads();
    if (s_x[r] < 0 && s_req[jm] == r && s_y[jm] < 0) {
        s_x[r] = jm;
        s_y[jm] = r;
    }
    __syncthreads();

    if (j == 0) {
        int n = 0;
        for (int rr = 0; rr < NB; rr++)
            if (s_x[rr] < 0) s_free[n++] = rr;
        s_nfree = n;
    }
    __syncthreads();

    // exact shortest augmenting path per free row
    double vj = s_v[j];
    int nfree = s_nfree;
    int lane = j & 31, warp = j >> 5;

    for (int f = 0; f < nfree; f++) {
        int cur = s_free[f];
        double shortest = DBL_MAX;
        int pathreg = cur;
        bool rem = true;
        bool inSR = (j == cur);
        int i = cur;
        double bvj = -s_u[cur] - vj;
        double minv = 0.0;
        int sink = -1;
        int par = 0;

        while (true) {
            float cf = Cb[(size_t)i * NB + j];
            if (rem) {
                double rd = (double)cf + bvj;
                if (rd < shortest) { shortest = rd; pathreg = i; }
            }
            unsigned long long key = rem ? packkey(shortest, j) : ~0ull;
#pragma unroll
            for (int o = 16; o; o >>= 1) {
                unsigned long long ko = __shfl_xor_sync(FULLM, key, o);
                if (ko < key) key = ko;
            }
            if (lane == 0) s_wm[par][warp] = key;
            __syncthreads();
            unsigned long long mn = s_wm[par][0];
#pragma unroll
            for (int w = 1; w < 8; w++) {
                unsigned long long t2 = s_wm[par][w];
                if (t2 < mn) mn = t2;
            }
            par ^= 1;
            int jpos = (int)(mn & 0xFF);
            minv = unpackval(mn);
            if (j == jpos) {
                rem = false;
                s_srec[j] = minv;
                s_path[j] = pathreg;
            }
            int r4c = s_y[jpos];
            if (r4c < 0) { sink = jpos; break; }
            i = r4c;
            if (j == i) inSR = true;
            bvj = minv - s_u[i] - vj;
        }
        __syncthreads();

        if (!rem) vj -= minv - s_srec[j];
        if (inSR) {
            if (j == cur) s_u[j] += minv;
            else s_u[j] += minv - s_srec[s_x[j]];
        }
        __syncthreads();

        if (j == 0) {
            int jj = sink;
            while (true) {
                int i2 = s_path[jj];
                s_y[jj] = i2;
                int t2 = s_x[i2];
                s_x[i2] = jj;
                jj = t2;
                if (i2 == cur) break;
            }
        }
        __syncthreads();
    }

    out_matches[b * 512 + j]       = (float)j;
    out_matches[b * 512 + 256 + j] = (float)s_x[j];
}

// ---------------- launch ----------------
extern "C" void kernel_launch(void* const* d_in, const int* in_sizes, int n_in,
                              void* d_out, int out_size) {
    const float* theta = (const float*)d_in[0];
    const float* feat1 = (const float*)d_in[1];
    const float* feat2 = (const float*)d_in[2];
    float* C = (float*)d_out;
    float* matches = C + (size_t)2048 * 2048;

    kA<<<33, 256>>>(theta, feat1, feat2, C);
    k3_fused<<<232, 256>>>(feat1, feat2, C, matches);
}

// round 17
// speedup vs baseline: 1.0524x; 1.0253x over previous
#include <cuda_runtime.h>
#include <math.h>
#include <float.h>

#define BN_TOTAL 2048
#define NB 256
#define FULLM 0xffffffffu

// ---------------- device scratch ----------------
__device__ float2 g_p2[BN_TOTAL];
__device__ float4 g_L[BN_TOTAL];
__device__ float  g_sub[8][NB][NB];   // diag blocks: desc-only after kA, final after kFix

// ---------------- serial Jacobi (3x3) ---------------
__device__ void jacobi_sym(double* A, double* V, int n) {
    for (int i = 0; i < n; i++)
        for (int j = 0; j < n; j++)
            V[i * n + j] = (i == j) ? 1.0 : 0.0;
    double fro2 = 0.0;
    for (int i = 0; i < n * n; i++) fro2 += A[i] * A[i];
    double thresh = 1e-28 * fro2 + 1e-300;
    for (int sweep = 0; sweep < 10; sweep++) {
        double off = 0.0;
        for (int p = 0; p < n - 1; p++)
            for (int q = p + 1; q < n; q++)
                off += A[p * n + q] * A[p * n + q];
        if (off < thresh) break;
        for (int p = 0; p < n - 1; p++) {
            for (int q = p + 1; q < n; q++) {
                double apq = A[p * n + q];
                if (fabs(apq) < 1e-300) continue;
                double app = A[p * n + p], aqq = A[q * n + q];
                double theta = (aqq - app) / (2.0 * apq);
                double t = ((theta >= 0.0) ? 1.0 : -1.0) /
                           (fabs(theta) + sqrt(theta * theta + 1.0));
                double c = 1.0 / sqrt(t * t + 1.0);
                double s = t * c;
                for (int k = 0; k < n; k++) {
                    double akp = A[k * n + p], akq = A[k * n + q];
                    A[k * n + p] = c * akp - s * akq;
                    A[k * n + q] = s * akp + c * akq;
                }
                for (int k = 0; k < n; k++) {
                    double apk = A[p * n + k], aqk = A[q * n + k];
                    A[p * n + k] = c * apk - s * aqk;
                    A[q * n + k] = s * apk + c * aqk;
                }
                for (int k = 0; k < n; k++) {
                    double vkp = V[k * n + p], vkq = V[k * n + q];
                    V[k * n + p] = c * vkp - s * vkq;
                    V[k * n + q] = s * vkp + c * vkq;
                }
            }
        }
    }
}

__device__ double block_reduce_sum(double v, double* sred) {
    int t = threadIdx.x;
    sred[t] = v;
    __syncthreads();
    for (int o = 128; o > 0; o >>= 1) {
        if (t < o) sred[t] += sred[t + o];
        __syncthreads();
    }
    double r = sred[0];
    __syncthreads();
    return r;
}

// ---------------- model fit body (kA block 32) ----------------
__device__ void model_fit_body(const float* __restrict__ theta,
                               const float* __restrict__ feat1,
                               const float* __restrict__ feat2,
                               double* sred, double* sh_AtA, double* sh_F) {
    int t = threadIdx.x;

    double th = (double)theta[0];
    double c = cos(th), s = sin(th);

    float2 p1l[8], p2l[8];
    double s1x = 0, s1y = 0, s2x = 0, s2y = 0;
#pragma unroll
    for (int k = 0; k < 8; k++) {
        int idx = t + (k << 8);
        const float* f1p = feat1 + (size_t)idx * 130;
        const float* f2p = feat2 + (size_t)idx * 130;
        float p1x = truncf(f2p[0]);
        float p1y = truncf(f2p[1]);
        double ax = (double)f1p[0] - 320.0;
        double ay = 240.0 - (double)f1p[1];
        double calx = rint(c * ax - s * ay);
        double caly = rint(s * ax + c * ay);
        float p2x = (float)trunc(calx + 320.0);
        float p2y = (float)trunc(240.0 - caly);
        p1l[k] = make_float2(p1x, p1y);
        p2l[k] = make_float2(p2x, p2y);
        g_p2[idx] = p2l[k];
        s1x += p1x; s1y += p1y; s2x += p2x; s2y += p2y;
    }
    double m1x = block_reduce_sum(s1x, sred) * (1.0 / 2048.0);
    double m1y = block_reduce_sum(s1y, sred) * (1.0 / 2048.0);
    double m2x = block_reduce_sum(s2x, sred) * (1.0 / 2048.0);
    double m2y = block_reduce_sum(s2y, sred) * (1.0 / 2048.0);

    double a1 = 0, a2 = 0;
#pragma unroll
    for (int k = 0; k < 8; k++) {
        double dx = (double)p1l[k].x - m1x, dy = (double)p1l[k].y - m1y;
        a1 += sqrt(dx * dx + dy * dy);
        double ex = (double)p2l[k].x - m2x, ey = (double)p2l[k].y - m2y;
        a2 += sqrt(ex * ex + ey * ey);
    }
    double d1 = block_reduce_sum(a1, sred) * (1.0 / 2048.0);
    double d2 = block_reduce_sum(a2, sred) * (1.0 / 2048.0);
    double sc1 = sqrt(2.0) / d1;
    double sc2 = sqrt(2.0) / d2;

    double m[45];
#pragma unroll
    for (int e = 0; e < 45; e++) m[e] = 0.0;
#pragma unroll
    for (int k = 0; k < 8; k++) {
        double u1 = ((double)p1l[k].x - m1x) * sc1;
        double v1 = ((double)p1l[k].y - m1y) * sc1;
        double u2 = ((double)p2l[k].x - m2x) * sc2;
        double v2 = ((double)p2l[k].y - m2y) * sc2;
        double a[9] = {u2 * u1, u2 * v1, u2, v2 * u1, v2 * v1, v2, u1, v1, 1.0};
        int e = 0;
#pragma unroll
        for (int p = 0; p < 9; p++)
#pragma unroll
            for (int q = p; q < 9; q++)
                m[e++] += a[p] * a[q];
    }
    if (t < 45) sh_AtA[t] = 0.0;
    __syncthreads();
    int lane = t & 31;
#pragma unroll
    for (int e = 0; e < 45; e++) {
        double v = m[e];
        for (int o = 16; o; o >>= 1) v += __shfl_down_sync(FULLM, v, o);
        if (lane == 0) atomicAdd(&sh_AtA[e], v);
    }
    __syncthreads();

    if (t == 0) {
        double A[81];
        {
            int e = 0;
            for (int p = 0; p < 9; p++)
                for (int q = p; q < 9; q++) {
                    A[p * 9 + q] = sh_AtA[e];
                    A[q * 9 + p] = sh_AtA[e];
                    e++;
                }
        }
        double L[81], dinv[9];
        for (int cc = 0; cc < 9; cc++) {
            double d = A[cc * 9 + cc];
            for (int k = 0; k < cc; k++) d -= L[cc * 9 + k] * L[cc * 9 + k];
            double lc = sqrt(d);
            L[cc * 9 + cc] = lc;
            double invl = 1.0 / lc;
            dinv[cc] = invl;
            for (int r = cc + 1; r < 9; r++) {
                double s2 = A[r * 9 + cc];
                for (int k = 0; k < cc; k++) s2 -= L[r * 9 + k] * L[cc * 9 + k];
                L[r * 9 + cc] = s2 * invl;
            }
        }
        double x[9];
        for (int i = 0; i < 9; i++) x[i] = 1.0 / (double)(i + 1);
        for (int it = 0; it < 25; it++) {
            double z[9], y[9];
            for (int r = 0; r < 9; r++) {
                double acc = x[r];
                for (int k = 0; k < r; k++) acc -= L[r * 9 + k] * z[k];
                z[r] = acc * dinv[r];
            }
            for (int r = 8; r >= 0; r--) {
                double acc = z[r];
                for (int k = r + 1; k < 9; k++) acc -= L[k * 9 + r] * y[k];
                y[r] = acc * dinv[r];
            }
            double nrm = 0.0;
            for (int i = 0; i < 9; i++) nrm += y[i] * y[i];
            double inv = 1.0 / sqrt(nrm);
            for (int i = 0; i < 9; i++) x[i] = y[i] * inv;
        }
        double F[9];
        for (int i = 0; i < 9; i++) F[i] = x[i];

        double G[9], V3[9];
        for (int r = 0; r < 3; r++)
            for (int cc = 0; cc < 3; cc++) {
                double acc = 0;
                for (int kk = 0; kk < 3; kk++) acc += F[kk * 3 + r] * F[kk * 3 + cc];
                G[r * 3 + cc] = acc;
            }
        jacobi_sym(G, V3, 3);
        int mi3 = 0;
        for (int i = 1; i < 3; i++)
            if (G[i * 3 + i] < G[mi3 * 3 + mi3]) mi3 = i;
        double v3[3] = {V3[0 * 3 + mi3], V3[1 * 3 + mi3], V3[2 * 3 + mi3]};
        double Fv[3];
        for (int r = 0; r < 3; r++)
            Fv[r] = F[r * 3 + 0] * v3[0] + F[r * 3 + 1] * v3[1] + F[r * 3 + 2] * v3[2];
        double F2[9];
        for (int r = 0; r < 3; r++)
            for (int cc = 0; cc < 3; cc++)
                F2[r * 3 + cc] = F[r * 3 + cc] - Fv[r] * v3[cc];

        double M1[9];
        for (int cc = 0; cc < 3; cc++) {
            M1[0 * 3 + cc] = sc2 * F2[0 * 3 + cc];
            M1[1 * 3 + cc] = sc2 * F2[1 * 3 + cc];
            M1[2 * 3 + cc] = (-sc2 * m2x) * F2[0 * 3 + cc] +
                             (-sc2 * m2y) * F2[1 * 3 + cc] + F2[2 * 3 + cc];
        }
        double M[9];
        for (int r = 0; r < 3; r++) {
            M[r * 3 + 0] = M1[r * 3 + 0] * sc1;
            M[r * 3 + 1] = M1[r * 3 + 1] * sc1;
            M[r * 3 + 2] = M1[r * 3 + 0] * (-sc1 * m1x) +
                           M1[r * 3 + 1] * (-sc1 * m1y) + M1[r * 3 + 2];
        }
        double inv = 1.0 / M[8];
        for (int i = 0; i < 9; i++) sh_F[i] = M[i] * inv;
    }
    __syncthreads();

#pragma unroll
    for (int k = 0; k < 8; k++) {
        int idx = t + (k << 8);
        double px = (double)p1l[k].x, py = (double)p1l[k].y;
        double L0 = px * sh_F[0] + py * sh_F[3] + sh_F[6];
        double L1 = px * sh_F[1] + py * sh_F[4] + sh_F[7];
        double L2 = px * sh_F[2] + py * sh_F[5] + sh_F[8];
        g_L[idx] = make_float4((float)L0, (float)L1, (float)L2, 0.0f);
    }
}

// ---------------- cost tile body ----------------
__device__ __forceinline__ void k2_tile_body(const float* __restrict__ feat1,
                                             const float* __restrict__ feat2,
                                             float* __restrict__ C,
                                             int bi, int bj,
                                             bool add_kp, bool write_C, bool write_sub,
                                             float (*As)[128], float (*Bs)[128]) {
    int t = threadIdx.x;
    int tx = t & 15, ty = t >> 4;
    int lr = t & 127, lh = (t >> 7) << 2;

    float acc[8][8];
#pragma unroll
    for (int mm = 0; mm < 8; mm++)
#pragma unroll
        for (int nn = 0; nn < 8; nn++) acc[mm][nn] = 0.0f;

    const float* A0 = feat1 + (size_t)(bi + lr) * 130 + 2;
    const float* B0 = feat2 + (size_t)(bj + lr) * 130 + 2;

    for (int k0 = 0; k0 < 128; k0 += 8) {
        float2 a0 = *(const float2*)(A0 + k0 + lh);
        float2 a1 = *(const float2*)(A0 + k0 + lh + 2);
        float2 b0 = *(const float2*)(B0 + k0 + lh);
        float2 b1 = *(const float2*)(B0 + k0 + lh + 2);
        As[lh + 0][lr] = a0.x; As[lh + 1][lr] = a0.y;
        As[lh + 2][lr] = a1.x; As[lh + 3][lr] = a1.y;
        Bs[lh + 0][lr] = b0.x; Bs[lh + 1][lr] = b0.y;
        Bs[lh + 2][lr] = b1.x; Bs[lh + 3][lr] = b1.y;
        __syncthreads();
#pragma unroll
        for (int kk = 0; kk < 8; kk++) {
            float a[8], b[8];
            *(float4*)&a[0] = *(const float4*)&As[kk][ty << 3];
            *(float4*)&a[4] = *(const float4*)&As[kk][(ty << 3) + 4];
            *(float4*)&b[0] = *(const float4*)&Bs[kk][tx << 3];
            *(float4*)&b[4] = *(const float4*)&Bs[kk][(tx << 3) + 4];
#pragma unroll
            for (int mm = 0; mm < 8; mm++)
#pragma unroll
                for (int nn = 0; nn < 8; nn++)
                    acc[mm][nn] += fabsf(a[mm] - b[nn]);
        }
        __syncthreads();
    }

    if (add_kp) {
        float4 Lm[8];
        float2 Pn[8];
#pragma unroll
        for (int mm = 0; mm < 8; mm++) Lm[mm] = g_L[bi + (ty << 3) + mm];
#pragma unroll
        for (int nn = 0; nn < 8; nn++) Pn[nn] = g_p2[bj + (tx << 3) + nn];
#pragma unroll
        for (int mm = 0; mm < 8; mm++)
#pragma unroll
            for (int nn = 0; nn < 8; nn++)
                acc[mm][nn] += fabsf(Lm[mm].x * Pn[nn].x + Lm[mm].y * Pn[nn].y + Lm[mm].z);
    }

    int bb = bi >> 8;
    int ri0 = bi & 255, rj0 = bj & 255;
#pragma unroll
    for (int mm = 0; mm < 8; mm++) {
        float4 v0 = make_float4(acc[mm][0], acc[mm][1], acc[mm][2], acc[mm][3]);
        float4 v1 = make_float4(acc[mm][4], acc[mm][5], acc[mm][6], acc[mm][7]);
        if (write_C) {
            float* dst = C + (size_t)(bi + (ty << 3) + mm) * 2048 + bj + (tx << 3);
            ((float4*)dst)[0] = v0;
            ((float4*)dst)[1] = v1;
        }
        if (write_sub) {
            float* sd = &g_sub[bb][ri0 + (ty << 3) + mm][rj0 + (tx << 3)];
            ((float4*)sd)[0] = v0;
            ((float4*)sd)[1] = v1;
        }
    }
}

// ---------------- kA: 32 desc-only diag tiles || model fit -----------------
__global__ void __launch_bounds__(256) kA(const float* __restrict__ theta,
                                          const float* __restrict__ feat1,
                                          const float* __restrict__ feat2,
                                          float* __restrict__ C) {
    __shared__ float As[8][128];
    __shared__ float Bs[8][128];
    __shared__ double sred[256];
    __shared__ double sh_AtA[45];
    __shared__ double sh_F[9];

    if (blockIdx.x < 32) {
        int idx = blockIdx.x;
        int bb = idx >> 2;
        int ri = (idx >> 1) & 1;
        int rj = idx & 1;
        int bi = (bb << 8) + (ri << 7);
        int bj = (bb << 8) + (rj << 7);
        k2_tile_body(feat1, feat2, C, bi, bj,
                     /*add_kp=*/false, /*write_C=*/false, /*write_sub=*/true,
                     As, Bs);
        return;
    }
    model_fit_body(theta, feat1, feat2, sred, sh_AtA, sh_F);
}

// ---------------- kFix: add kp term to diag blocks, write g_sub + C --------
// 32 blocks: block idx -> batch bb = idx>>2, row chunk rc = idx&3 (64 rows)
__global__ void __launch_bounds__(256) kFix(float* __restrict__ C) {
    int bb = blockIdx.x >> 2;
    int rc = blockIdx.x & 3;
    int j = threadIdx.x;
    float2 p2 = g_p2[bb * NB + j];
    float* sub = &g_sub[bb][rc * 64][0];
    float* Cd = C + (size_t)(bb * NB + rc * 64) * 2048 + bb * NB;
#pragma unroll 4
    for (int i = 0; i < 64; i++) {
        float4 Li = g_L[bb * NB + rc * 64 + i];   // uniform broadcast
        float cv = sub[(size_t)i * NB + j] +
                   fabsf(Li.x * p2.x + Li.y * p2.y + Li.z);
        sub[(size_t)i * NB + j] = cv;
        Cd[(size_t)i * 2048 + j] = cv;
    }
}

// ---------------- k3_fused: blocks 0-7 LAP (R14), 8-231 off-diag tiles -----
__device__ __forceinline__ unsigned long long packkey(double v, int j) {
    unsigned long long b = (unsigned long long)__double_as_longlong(v);
    b = (b & 0x8000000000000000ull) ? ~b : (b | 0x8000000000000000ull);
    return (b & ~0xFFull) | (unsigned)j;
}
__device__ __forceinline__ double unpackval(unsigned long long k) {
    k &= ~0xFFull;
    if (k & 0x8000000000000000ull) k ^= 0x8000000000000000ull;
    else k = ~k;
    return __longlong_as_double((long long)k);
}

__global__ void __launch_bounds__(256) k3_fused(const float* __restrict__ feat1,
                                                const float* __restrict__ feat2,
                                                float* __restrict__ C,
                                                float* __restrict__ out_matches) {
    __shared__ float As[8][128];
    __shared__ float Bs[8][128];
    __shared__ double s_v[NB], s_u[NB], s_srec[NB];
    __shared__ int s_x[NB], s_y[NB], s_path[NB], s_free[NB];
    __shared__ int s_rowwin[NB], s_req[NB];
    __shared__ unsigned long long s_wm[2][8];
    __shared__ int s_nfree;

    if (blockIdx.x >= 8) {
        int idx = blockIdx.x - 8;           // 0..223
        int rrow = idx / 14;
        int c14 = idx % 14;
        int bb = rrow >> 1;
        int cc = (c14 >= (bb << 1)) ? c14 + 2 : c14;
        int bi = rrow << 7;
        int bj = cc << 7;
        k2_tile_body(feat1, feat2, C, bi, bj,
                     /*add_kp=*/true, /*write_C=*/true, /*write_sub=*/false,
                     As, Bs);
        return;
    }

    // ---- LAP on diagonal block (exact R14 engine) ----
    int j = threadIdx.x;
    int b = blockIdx.x;
    const float* Cb = &g_sub[b][0][0];

    // Phase A: v[j] = colmin + argmin row; greedy round 1
    float cm = FLT_MAX;
    int am = 0;
#pragma unroll 8
    for (int i = 0; i < NB; i++) {
        float cv = Cb[(size_t)i * NB + j];
        if (cv < cm) { cm = cv; am = i; }
    }
    s_v[j] = (double)cm;
    s_x[j] = -1;
    s_y[j] = -1;
    s_rowwin[j] = 0x7fffffff;
    s_req[j] = 0x7fffffff;
    __syncthreads();
    atomicMin(&s_rowwin[am], j);
    __syncthreads();
    if (s_rowwin[am] == j) { s_x[am] = j; s_y[j] = am; }
    __syncthreads();

    // Phase B: u[r] = rowmin + argmin; greedy round 2
    int r = j;
    double um = DBL_MAX;
    int jm = 0;
    {
        const float* rp = Cb + (size_t)r * NB;
        for (int q = 0; q < NB; q++) {
            double rc = (double)rp[q] - s_v[q];
            if (rc < um) { um = rc; jm = q; }
        }
    }
    s_u[r] = um;
    if (s_x[r] < 0 && s_y[jm] < 0) atomicMin(&s_req[jm], r);
    __syncthreads();
    if (s_x[r] < 0 && s_req[jm] == r && s_y[jm] < 0) {
        s_x[r] = jm;
        s_y[jm] = r;
    }
    __syncthreads();

    if (j == 0) {
        int n = 0;
        for (int rr = 0; rr < NB; rr++)
            if (s_x[rr] < 0) s_free[n++] = rr;
        s_nfree = n;
    }
    __syncthreads();

    // exact shortest augmenting path per free row
    double vj = s_v[j];
    int nfree = s_nfree;
    int lane = j & 31, warp = j >> 5;

    for (int f = 0; f < nfree; f++) {
        int cur = s_free[f];
        double shortest = DBL_MAX;
        int pathreg = cur;
        bool rem = true;
        bool inSR = (j == cur);
        int i = cur;
        double bvj = -s_u[cur] - vj;
        double minv = 0.0;
        int sink = -1;
        int par = 0;

        while (true) {
            float cf = Cb[(size_t)i * NB + j];
            if (rem) {
                double rd = (double)cf + bvj;
                if (rd < shortest) { shortest = rd; pathreg = i; }
            }
            unsigned long long key = rem ? packkey(shortest, j) : ~0ull;
#pragma unroll
            for (int o = 16; o; o >>= 1) {
                unsigned long long ko = __shfl_xor_sync(FULLM, key, o);
                if (ko < key) key = ko;
            }
            if (lane == 0) s_wm[par][warp] = key;
            __syncthreads();
            unsigned long long mn = s_wm[par][0];
#pragma unroll
            for (int w = 1; w < 8; w++) {
                unsigned long long t2 = s_wm[par][w];
                if (t2 < mn) mn = t2;
            }
            par ^= 1;
            int jpos = (int)(mn & 0xFF);
            minv = unpackval(mn);
            if (j == jpos) {
                rem = false;
                s_srec[j] = minv;
                s_path[j] = pathreg;
            }
            int r4c = s_y[jpos];
            if (r4c < 0) { sink = jpos; break; }
            i = r4c;
            if (j == i) inSR = true;
            bvj = minv - s_u[i] - vj;
        }
        __syncthreads();

        if (!rem) vj -= minv - s_srec[j];
        if (inSR) {
            if (j == cur) s_u[j] += minv;
            else s_u[j] += minv - s_srec[s_x[j]];
        }
        __syncthreads();

        if (j == 0) {
            int jj = sink;
            while (true) {
                int i2 = s_path[jj];
                s_y[jj] = i2;
                int t2 = s_x[i2];
                s_x[i2] = jj;
                jj = t2;
                if (i2 == cur) break;
            }
        }
        __syncthreads();
    }

    out_matches[b * 512 + j]       = (float)j;
    out_matches[b * 512 + 256 + j] = (float)s_x[j];
}

// ---------------- launch ----------------
extern "C" void kernel_launch(void* const* d_in, const int* in_sizes, int n_in,
                              void* d_out, int out_size) {
    const float* theta = (const float*)d_in[0];
    const float* feat1 = (const float*)d_in[1];
    const float* feat2 = (const float*)d_in[2];
    float* C = (float*)d_out;
    float* matches = C + (size_t)2048 * 2048;

    kA<<<33, 256>>>(theta, feat1, feat2, C);
    kFix<<<32, 256>>>(C);
    k3_fused<<<232, 256>>>(feat1, feat2, C, matches);
}